// round 1
// baseline (speedup 1.0000x reference)
#include <cuda_runtime.h>

#define NT   8192    // tokens = B*S
#define DD   1024    // D
#define GHA  512     // gating hidden 1
#define GHB  256     // gating hidden 2
#define NE   8       // experts
#define HH   2048    // expert hidden H
#define MAX_MTILES 136  // sum ceil(cnt_e/128) <= 16384/128 + 8

// ---------------- scratch (static device globals; no allocation) ----------
__device__ float g_h1[NT * GHA];            // 16 MB
__device__ float g_h2[NT * GHB];            //  8 MB
__device__ float g_wval[NT * 2];
__device__ int   g_cnt[NE];
__device__ int   g_list[NE * NT];           // pair id = t*2+k
__device__ float g_pair[(size_t)NT * 2 * HH];  // 128 MB
__device__ float g_moe[(size_t)NT * HH];       //  64 MB

// ---------------- zero counters -------------------------------------------
__global__ void zero_cnt_kernel() {
    if (threadIdx.x < NE) g_cnt[threadIdx.x] = 0;
}

// ---------------- classic 128x128x8 SGEMM, C = op(A@B + bias) -------------
// A: [M,K] row-major, B: [K,N] row-major, grid = (N/128, M/128), 256 thr
template<bool RELU>
__launch_bounds__(256, 2)
__global__ void sgemm_bias_kernel(const float* __restrict__ A,
                                  const float* __restrict__ B,
                                  const float* __restrict__ bias,
                                  float* __restrict__ C,
                                  int M, int N, int K) {
    __shared__ float As[8][128];
    __shared__ float Bs[8][128];
    const int tid = threadIdx.x;
    const int bx = blockIdx.x, by = blockIdx.y;

    const float* Ab = A + (size_t)by * 128 * K;
    const float* Bb = B + (size_t)bx * 128;

    const int arow = tid >> 1;            // 0..127
    const int acol = (tid & 1) * 4;       // 0 or 4
    const int brow = tid >> 5;            // 0..7
    const int bcol = (tid & 31) * 4;      // 0..124
    const int ty = tid >> 4;              // 0..15
    const int tx = tid & 15;              // 0..15

    float acc[8][8] = {};

    for (int k0 = 0; k0 < K; k0 += 8) {
        float4 av = *(const float4*)(Ab + (size_t)arow * K + k0 + acol);
        As[acol + 0][arow] = av.x;
        As[acol + 1][arow] = av.y;
        As[acol + 2][arow] = av.z;
        As[acol + 3][arow] = av.w;
        float4 bv = *(const float4*)(Bb + (size_t)(k0 + brow) * N + bcol);
        *(float4*)&Bs[brow][bcol] = bv;
        __syncthreads();
        #pragma unroll
        for (int kk = 0; kk < 8; kk++) {
            float fa[8], fb[8];
            #pragma unroll
            for (int i = 0; i < 8; i++) fa[i] = As[kk][ty * 8 + i];
            #pragma unroll
            for (int j = 0; j < 8; j++) fb[j] = Bs[kk][tx * 8 + j];
            #pragma unroll
            for (int i = 0; i < 8; i++)
                #pragma unroll
                for (int j = 0; j < 8; j++)
                    acc[i][j] = fmaf(fa[i], fb[j], acc[i][j]);
        }
        __syncthreads();
    }

    #pragma unroll
    for (int i = 0; i < 8; i++) {
        int m = by * 128 + ty * 8 + i;
        float* crow = C + (size_t)m * N + bx * 128 + tx * 8;
        const float* brow2 = bias + bx * 128 + tx * 8;
        #pragma unroll
        for (int j = 0; j < 8; j++) {
            float v = acc[i][j] + brow2[j];
            if (RELU) v = fmaxf(v, 0.f);
            crow[j] = v;
        }
    }
}

// ---------------- gating: logits -> top2 -> renorm weights + routing ------
// one warp per token
__global__ void gating_kernel(const int* __restrict__ ftypes,
                              const float* __restrict__ gw3,   // [256,8]
                              const float* __restrict__ gb3,   // [8]
                              const float* __restrict__ temb,  // [3,128]
                              const float* __restrict__ tw,    // [128,8]
                              const float* __restrict__ tb) {  // [8]
    int gwarp = (blockIdx.x * blockDim.x + threadIdx.x) >> 5;
    int lane = threadIdx.x & 31;
    if (gwarp >= NT) return;
    const int t = gwarp;

    float acc[NE] = {};
    const float* hrow = g_h2 + (size_t)t * GHB;
    for (int j = lane; j < GHB; j += 32) {
        float hv = hrow[j];
        const float* g = gw3 + j * NE;
        #pragma unroll
        for (int e = 0; e < NE; e++) acc[e] = fmaf(hv, g[e], acc[e]);
    }
    int ft = ftypes[t];
    const float* te = temb + ft * 128;
    for (int j = lane; j < 128; j += 32) {
        float tv = te[j];
        const float* w = tw + j * NE;
        #pragma unroll
        for (int e = 0; e < NE; e++) acc[e] = fmaf(tv, w[e], acc[e]);
    }
    #pragma unroll
    for (int off = 16; off; off >>= 1)
        #pragma unroll
        for (int e = 0; e < NE; e++)
            acc[e] += __shfl_xor_sync(0xffffffffu, acc[e], off);

    if (lane == 0) {
        float logits[NE];
        #pragma unroll
        for (int e = 0; e < NE; e++) logits[e] = acc[e] + gb3[e] + tb[e];
        // top-2 (jax top_k tie-break: lower index wins)
        int i0 = 0;
        #pragma unroll
        for (int e = 1; e < NE; e++) if (logits[e] > logits[i0]) i0 = e;
        int i1 = (i0 == 0) ? 1 : 0;
        #pragma unroll
        for (int e = 0; e < NE; e++) {
            if (e == i0 || e == i1) continue;
            if (logits[e] > logits[i1]) i1 = e;
        }
        // tie-break exactness: ensure i1 is earliest index with its value
        float z0 = logits[i0], z1 = logits[i1];
        // renormalized top-2 softmax weights: softmax denominator cancels
        float r = expf(z1 - z0);           // in (0,1]
        float inv = 1.f / (1.f + r);
        g_wval[t * 2 + 0] = inv;
        g_wval[t * 2 + 1] = r * inv;
        int s0 = atomicAdd(&g_cnt[i0], 1);
        g_list[i0 * NT + s0] = t * 2 + 0;
        int s1 = atomicAdd(&g_cnt[i1], 1);
        g_list[i1 * NT + s1] = t * 2 + 1;
    }
}

// ---------------- grouped expert GEMM: gathered A rows, scattered C -------
// pair_out[pid, :] = x[tok] @ ew[e] + eb[e];  grid = (HH/128, MAX_MTILES)
__launch_bounds__(256, 2)
__global__ void expert_gemm_kernel(const float* __restrict__ x,
                                   const float* __restrict__ ew,   // [E,D,H]
                                   const float* __restrict__ eb) { // [E,H]
    // map flat m-slot -> (expert, tile)
    int flat = blockIdx.y;
    int cnts[NE];
    #pragma unroll
    for (int i = 0; i < NE; i++) cnts[i] = g_cnt[i];
    int e = 0, base = 0, mt = 0;
    bool found = false;
    #pragma unroll
    for (int i = 0; i < NE; i++) {
        int tiles = (cnts[i] + 127) >> 7;
        if (!found && flat < base + tiles) { e = i; mt = flat - base; found = true; }
        base += tiles;
    }
    if (!found) return;
    const int cnt = cnts[e];

    __shared__ int s_pid[128];
    __shared__ int s_tok[128];
    __shared__ float As[8][128];
    __shared__ float Bs[8][128];

    const int tid = threadIdx.x;
    if (tid < 128) {
        int idx = mt * 128 + tid;
        int pid = (idx < cnt) ? g_list[e * NT + idx] : -1;
        s_pid[tid] = pid;
        s_tok[tid] = (pid >= 0) ? (pid >> 1) : 0;
    }
    __syncthreads();

    const int bx = blockIdx.x;
    const float* Bb = ew + (size_t)e * DD * HH + (size_t)bx * 128;

    const int arow = tid >> 1;
    const int acol = (tid & 1) * 4;
    const int brow = tid >> 5;
    const int bcol = (tid & 31) * 4;
    const int ty = tid >> 4;
    const int tx = tid & 15;

    float acc[8][8] = {};

    for (int k0 = 0; k0 < DD; k0 += 8) {
        int tok = s_tok[arow];
        float4 av = *(const float4*)(x + (size_t)tok * DD + k0 + acol);
        As[acol + 0][arow] = av.x;
        As[acol + 1][arow] = av.y;
        As[acol + 2][arow] = av.z;
        As[acol + 3][arow] = av.w;
        float4 bv = *(const float4*)(Bb + (size_t)(k0 + brow) * HH + bcol);
        *(float4*)&Bs[brow][bcol] = bv;
        __syncthreads();
        #pragma unroll
        for (int kk = 0; kk < 8; kk++) {
            float fa[8], fb[8];
            #pragma unroll
            for (int i = 0; i < 8; i++) fa[i] = As[kk][ty * 8 + i];
            #pragma unroll
            for (int j = 0; j < 8; j++) fb[j] = Bs[kk][tx * 8 + j];
            #pragma unroll
            for (int i = 0; i < 8; i++)
                #pragma unroll
                for (int j = 0; j < 8; j++)
                    acc[i][j] = fmaf(fa[i], fb[j], acc[i][j]);
        }
        __syncthreads();
    }

    const float* biasp = eb + (size_t)e * HH + bx * 128 + tx * 8;
    #pragma unroll
    for (int i = 0; i < 8; i++) {
        int pid = s_pid[ty * 8 + i];
        if (pid < 0) continue;
        float* crow = g_pair + (size_t)pid * HH + bx * 128 + tx * 8;
        #pragma unroll
        for (int j = 0; j < 8; j++)
            crow[j] = acc[i][j] + biasp[j];
    }
}

// ---------------- combine: moe = relu(w0*pair0 + w1*pair1) ----------------
__global__ void combine_kernel() {
    int idx = blockIdx.x * blockDim.x + threadIdx.x;   // over NT*HH/4
    int t = idx / (HH / 4);
    int h4 = idx % (HH / 4);
    float w0 = g_wval[t * 2 + 0];
    float w1 = g_wval[t * 2 + 1];
    const float4* p = (const float4*)g_pair;
    float4 a = p[(size_t)(t * 2 + 0) * (HH / 4) + h4];
    float4 b = p[(size_t)(t * 2 + 1) * (HH / 4) + h4];
    float4 o;
    o.x = fmaxf(fmaf(w0, a.x, w1 * b.x), 0.f);
    o.y = fmaxf(fmaf(w0, a.y, w1 * b.y), 0.f);
    o.z = fmaxf(fmaf(w0, a.z, w1 * b.z), 0.f);
    o.w = fmaxf(fmaf(w0, a.w, w1 * b.w), 0.f);
    ((float4*)g_moe)[(size_t)t * (HH / 4) + h4] = o;
}

// ---------------- launch ---------------------------------------------------
extern "C" void kernel_launch(void* const* d_in, const int* in_sizes, int n_in,
                              void* d_out, int out_size) {
    const float* x     = (const float*)d_in[0];
    const int*   ft    = (const int*)  d_in[1];
    const float* gw1   = (const float*)d_in[2];
    const float* gb1   = (const float*)d_in[3];
    const float* gw2   = (const float*)d_in[4];
    const float* gb2   = (const float*)d_in[5];
    const float* gw3   = (const float*)d_in[6];
    const float* gb3   = (const float*)d_in[7];
    const float* temb  = (const float*)d_in[8];
    const float* tw    = (const float*)d_in[9];
    const float* tb    = (const float*)d_in[10];
    const float* ew    = (const float*)d_in[11];
    const float* eb    = (const float*)d_in[12];
    const float* ow    = (const float*)d_in[13];
    const float* ob    = (const float*)d_in[14];
    float* out = (float*)d_out;

    float *h1, *h2, *moe;
    cudaGetSymbolAddress((void**)&h1,  g_h1);
    cudaGetSymbolAddress((void**)&h2,  g_h2);
    cudaGetSymbolAddress((void**)&moe, g_moe);

    zero_cnt_kernel<<<1, 32>>>();

    // gating MLP
    sgemm_bias_kernel<true><<<dim3(GHA / 128, NT / 128), 256>>>(x,  gw1, gb1, h1, NT, GHA, DD);
    sgemm_bias_kernel<true><<<dim3(GHB / 128, NT / 128), 256>>>(h1, gw2, gb2, h2, NT, GHB, GHA);

    // routing
    gating_kernel<<<NT / 8, 256>>>(ft, gw3, gb3, temb, tw, tb);

    // selected-expert grouped GEMM (top-2 only; identical math to dense+gather)
    expert_gemm_kernel<<<dim3(HH / 128, MAX_MTILES), 256>>>(x, ew, eb);

    // combine + relu
    combine_kernel<<<(NT * (HH / 4)) / 256, 256>>>();

    // output projection
    sgemm_bias_kernel<false><<<dim3(DD / 128, NT / 128), 256>>>(moe, ow, ob, out, NT, DD, HH);
}

// round 3
// speedup vs baseline: 2.2055x; 2.2055x over previous
#include <cuda_runtime.h>
#include <cuda_bf16.h>
#include <cstdint>

#define NT   8192
#define DD   1024
#define GHA  512
#define GHB  256
#define NE   8
#define HH   2048
#define MAX_MTILES 136

typedef __nv_bfloat16 bf16;

// ---------------- scratch ---------------------------------------------------
__device__ bf16  g_xhi[NT * DD],  g_xlo[NT * DD];
__device__ bf16  g_h1hi[NT * GHA], g_h1lo[NT * GHA];
__device__ float g_h2[NT * GHB];
__device__ bf16  g_w1hi[GHA * DD], g_w1lo[GHA * DD];       // [GHA][DD]
__device__ bf16  g_w2hi[GHB * GHA], g_w2lo[GHB * GHA];     // [GHB][GHA]
__device__ bf16  g_ewhi[(size_t)NE * HH * DD], g_ewlo[(size_t)NE * HH * DD]; // [E][H][D]
__device__ bf16  g_owhi[DD * HH], g_owlo[DD * HH];         // [DD][HH]
__device__ float g_wval[NT * 2];
__device__ int   g_cnt[NE];
__device__ int   g_list[NE * NT];
__device__ float g_pair[(size_t)NT * 2 * HH];
__device__ bf16  g_moehi[(size_t)NT * HH], g_moelo[(size_t)NT * HH];

// ---------------- PTX helpers (sm_80+ baseline only) ------------------------
__device__ __forceinline__ uint32_t smem_u32(const void* p) {
    uint32_t a;
    asm("{ .reg .u64 t; cvta.to.shared.u64 t, %1; cvt.u32.u64 %0, t; }" : "=r"(a) : "l"(p));
    return a;
}
__device__ __forceinline__ void cp16(uint32_t s, const void* g) {
    asm volatile("cp.async.cg.shared.global [%0], [%1], 16;" :: "r"(s), "l"(g));
}
#define CP_COMMIT() asm volatile("cp.async.commit_group;" ::: "memory")
#define CP_WAIT1()  asm volatile("cp.async.wait_group 1;" ::: "memory")
#define CP_WAIT0()  asm volatile("cp.async.wait_group 0;" ::: "memory")

__device__ __forceinline__ void ldsm_x4(uint32_t* r, uint32_t a) {
    asm volatile("ldmatrix.sync.aligned.m8n8.x4.shared.b16 {%0,%1,%2,%3}, [%4];"
        : "=r"(r[0]), "=r"(r[1]), "=r"(r[2]), "=r"(r[3]) : "r"(a));
}
__device__ __forceinline__ void ldsm_x2(uint32_t* r, uint32_t a) {
    asm volatile("ldmatrix.sync.aligned.m8n8.x2.shared.b16 {%0,%1}, [%2];"
        : "=r"(r[0]), "=r"(r[1]) : "r"(a));
}
__device__ __forceinline__ void mma_bf16(float* c, const uint32_t* a, const uint32_t* b) {
    asm volatile("mma.sync.aligned.m16n8k16.row.col.f32.bf16.bf16.f32 "
        "{%0,%1,%2,%3}, {%4,%5,%6,%7}, {%8,%9}, {%0,%1,%2,%3};"
        : "+f"(c[0]), "+f"(c[1]), "+f"(c[2]), "+f"(c[3])
        : "r"(a[0]), "r"(a[1]), "r"(a[2]), "r"(a[3]), "r"(b[0]), "r"(b[1]));
}

// ---------------- small kernels ---------------------------------------------
__global__ void zero_cnt_kernel() { if (threadIdx.x < NE) g_cnt[threadIdx.x] = 0; }

__global__ void split_x_kernel(const float* __restrict__ x) {
    int i = blockIdx.x * blockDim.x + threadIdx.x;
    float v = x[i];
    bf16 h = __float2bfloat16(v);
    g_xhi[i] = h;
    g_xlo[i] = __float2bfloat16(v - __bfloat162float(h));
}

// in [R][C] fp32 (+z batch) -> out [C][R] bf16 hi/lo
__global__ void tsplit_kernel(const float* __restrict__ in, bf16* __restrict__ ohi,
                              bf16* __restrict__ olo, int R, int C) {
    __shared__ float t[32][33];
    size_t zoff = (size_t)blockIdx.z * R * C;
    in += zoff; ohi += zoff; olo += zoff;
    int c0 = blockIdx.x * 32, r0 = blockIdx.y * 32;
    for (int i = threadIdx.y; i < 32; i += 8)
        t[i][threadIdx.x] = in[(size_t)(r0 + i) * C + c0 + threadIdx.x];
    __syncthreads();
    for (int i = threadIdx.y; i < 32; i += 8) {
        float v = t[threadIdx.x][i];
        bf16 h = __float2bfloat16(v);
        size_t o = (size_t)(c0 + i) * R + r0 + threadIdx.x;
        ohi[o] = h;
        olo[o] = __float2bfloat16(v - __bfloat162float(h));
    }
}

// ---------------- gating: logits -> top2 -> routing --------------------------
__global__ void gating_kernel(const int* __restrict__ ftypes,
                              const float* __restrict__ gw3, const float* __restrict__ gb3,
                              const float* __restrict__ temb, const float* __restrict__ tw,
                              const float* __restrict__ tb) {
    int gwarp = (blockIdx.x * blockDim.x + threadIdx.x) >> 5;
    int lane = threadIdx.x & 31;
    if (gwarp >= NT) return;
    const int t = gwarp;
    float acc[NE] = {};
    const float* hrow = g_h2 + (size_t)t * GHB;
    for (int j = lane; j < GHB; j += 32) {
        float hv = hrow[j];
        const float* g = gw3 + j * NE;
        #pragma unroll
        for (int e = 0; e < NE; e++) acc[e] = fmaf(hv, g[e], acc[e]);
    }
    int ftv = ftypes[t];
    const float* te = temb + ftv * 128;
    for (int j = lane; j < 128; j += 32) {
        float tv = te[j];
        const float* w = tw + j * NE;
        #pragma unroll
        for (int e = 0; e < NE; e++) acc[e] = fmaf(tv, w[e], acc[e]);
    }
    #pragma unroll
    for (int off = 16; off; off >>= 1)
        #pragma unroll
        for (int e = 0; e < NE; e++) acc[e] += __shfl_xor_sync(0xffffffffu, acc[e], off);
    if (lane == 0) {
        float logits[NE];
        #pragma unroll
        for (int e = 0; e < NE; e++) logits[e] = acc[e] + gb3[e] + tb[e];
        int i0 = 0;
        #pragma unroll
        for (int e = 1; e < NE; e++) if (logits[e] > logits[i0]) i0 = e;
        int i1 = (i0 == 0) ? 1 : 0;
        #pragma unroll
        for (int e = 0; e < NE; e++) {
            if (e == i0 || e == i1) continue;
            if (logits[e] > logits[i1]) i1 = e;
        }
        float r = expf(logits[i1] - logits[i0]);
        float inv = 1.f / (1.f + r);
        g_wval[t * 2 + 0] = inv;
        g_wval[t * 2 + 1] = r * inv;
        int s0 = atomicAdd(&g_cnt[i0], 1); g_list[i0 * NT + s0] = t * 2 + 0;
        int s1 = atomicAdd(&g_cnt[i1], 1); g_list[i1 * NT + s1] = t * 2 + 1;
    }
}

// ---------------- bf16-split MMA GEMM (mma.sync m16n8k16) --------------------
// C[128,128] fp32 = (Ahi+Alo)[m,k] * (Bhi+Blo)[n,k]^T, 3-term split.
// A: [M,K] K-major; B: [N,K] K-major. grid = (N/128, Mtiles), 256 threads.
#define EPI_RELU_SPLIT 0
#define EPI_RELU_F32   1
#define EPI_F32        2
#define EPI_SCATTER    3

#define ROWB      80            // padded row stride in bytes (40 bf16)
#define TILES_OFF 1024
#define STAGE_SZ  40960
#define OA_HI 0
#define OA_LO 10240
#define OB_HI 20480
#define OB_LO 30720
#define SMEM_TOTAL (TILES_OFF + 2 * STAGE_SZ)   // 82944

template<int MODE, bool GATHER>
__global__ void __launch_bounds__(256, 1) mma_gemm(
    const bf16* __restrict__ Ahi, const bf16* __restrict__ Alo,
    const bf16* __restrict__ Bhi, const bf16* __restrict__ Blo,
    const float* __restrict__ bias,
    float* __restrict__ outf, bf16* __restrict__ outhi, bf16* __restrict__ outlo,
    int N, int K) {
    extern __shared__ char smem[];
    int* s_pid = (int*)smem;
    int* s_tok = (int*)(smem + 512);
    const int tid = threadIdx.x, lane = tid & 31, wid = tid >> 5;
    const int wm = wid >> 2, wn = wid & 3;
    const int nb = blockIdx.x;

    int mtile = blockIdx.y, e = 0;
    if (GATHER) {
        int flat = blockIdx.y, base = 0, cnt = 0;
        bool found = false;
        #pragma unroll
        for (int i = 0; i < NE; i++) {
            int c = g_cnt[i];
            int tiles = (c + 127) >> 7;
            if (!found && flat < base + tiles) { e = i; mtile = flat - base; cnt = c; found = true; }
            base += tiles;
        }
        if (!found) return;
        if (tid < 128) {
            int idx = mtile * 128 + tid;
            int pid = (idx < cnt) ? g_list[e * NT + idx] : -1;
            s_pid[tid] = pid;
            s_tok[tid] = (pid >= 0) ? (pid >> 1) : 0;
        }
        Bhi += (size_t)e * HH * DD;
        Blo += (size_t)e * HH * DD;
        bias += (size_t)e * HH;
        __syncthreads();
    }

    const uint32_t sb = smem_u32(smem) + TILES_OFF;

    // per-thread load slots: 2 rows x 1 segment for each of A/B hi/lo
    const int seg = tid & 3;               // 16B segment within 64B row
    const int r0 = tid >> 2;               // 0..63
    const int r1 = r0 + 64;
    size_t ar0 = GATHER ? (size_t)s_tok[r0] : ((size_t)mtile * 128 + r0);
    size_t ar1 = GATHER ? (size_t)s_tok[r1] : ((size_t)mtile * 128 + r1);
    size_t br0 = (size_t)nb * 128 + r0;
    size_t br1 = (size_t)nb * 128 + r1;
    const bf16* pAh0 = Ahi + ar0 * K + seg * 8;
    const bf16* pAh1 = Ahi + ar1 * K + seg * 8;
    const bf16* pAl0 = Alo + ar0 * K + seg * 8;
    const bf16* pAl1 = Alo + ar1 * K + seg * 8;
    const bf16* pBh0 = Bhi + br0 * K + seg * 8;
    const bf16* pBh1 = Bhi + br1 * K + seg * 8;
    const bf16* pBl0 = Blo + br0 * K + seg * 8;
    const bf16* pBl1 = Blo + br1 * K + seg * 8;
    const uint32_t so0 = r0 * ROWB + seg * 16;
    const uint32_t so1 = r1 * ROWB + seg * 16;

    float acc[4][4][4] = {};
    const int niter = K >> 5;

    // prologue: stage 0
    {
        cp16(sb + OA_HI + so0, pAh0); cp16(sb + OA_HI + so1, pAh1);
        cp16(sb + OA_LO + so0, pAl0); cp16(sb + OA_LO + so1, pAl1);
        cp16(sb + OB_HI + so0, pBh0); cp16(sb + OB_HI + so1, pBh1);
        cp16(sb + OB_LO + so0, pBl0); cp16(sb + OB_LO + so1, pBl1);
        CP_COMMIT();
    }

    for (int it = 0; it < niter; it++) {
        if (it + 1 < niter) {
            const uint32_t st = sb + ((it + 1) & 1) * STAGE_SZ;
            const int ko = (it + 1) << 5;
            cp16(st + OA_HI + so0, pAh0 + ko); cp16(st + OA_HI + so1, pAh1 + ko);
            cp16(st + OA_LO + so0, pAl0 + ko); cp16(st + OA_LO + so1, pAl1 + ko);
            cp16(st + OB_HI + so0, pBh0 + ko); cp16(st + OB_HI + so1, pBh1 + ko);
            cp16(st + OB_LO + so0, pBl0 + ko); cp16(st + OB_LO + so1, pBl1 + ko);
            CP_COMMIT();
            CP_WAIT1();
        } else {
            CP_WAIT0();
        }
        __syncthreads();

        const uint32_t st = sb + (it & 1) * STAGE_SZ;
        #pragma unroll
        for (int ks = 0; ks < 2; ks++) {
            uint32_t ah[4][4], al[4][4], bh[4][2], bl[4][2];
            const int acol = (ks * 16 + (lane >> 4) * 8) * 2;
            const int arow = wm * 64 + (lane & 15);
            #pragma unroll
            for (int mt = 0; mt < 4; mt++) {
                uint32_t ad = st + (arow + mt * 16) * ROWB + acol;
                ldsm_x4(ah[mt], ad + OA_HI);
                ldsm_x4(al[mt], ad + OA_LO);
            }
            const int bcol = (ks * 16 + ((lane >> 3) & 1) * 8) * 2;
            const int brow = wn * 32 + (lane & 7);
            #pragma unroll
            for (int nt = 0; nt < 4; nt++) {
                uint32_t bd = st + (brow + nt * 8) * ROWB + bcol;
                ldsm_x2(bh[nt], bd + OB_HI);
                ldsm_x2(bl[nt], bd + OB_LO);
            }
            #pragma unroll
            for (int mt = 0; mt < 4; mt++)
                #pragma unroll
                for (int nt = 0; nt < 4; nt++) {
                    mma_bf16(acc[mt][nt], ah[mt], bh[nt]);
                    mma_bf16(acc[mt][nt], ah[mt], bl[nt]);
                    mma_bf16(acc[mt][nt], al[mt], bh[nt]);
                }
        }
        __syncthreads();
    }

    // -------- epilogue --------
    #pragma unroll
    for (int mt = 0; mt < 4; mt++) {
        const int mloc0 = wm * 64 + mt * 16 + (lane >> 2);
        #pragma unroll
        for (int half = 0; half < 2; half++) {
            const int mloc = mloc0 + half * 8;
            int pid = 0;
            if (GATHER) { pid = s_pid[mloc]; if (pid < 0) continue; }
            #pragma unroll
            for (int nt = 0; nt < 4; nt++) {
                const int c0 = nb * 128 + wn * 32 + nt * 8 + (lane & 3) * 2;
                float v0 = acc[mt][nt][half * 2 + 0] + bias[c0];
                float v1 = acc[mt][nt][half * 2 + 1] + bias[c0 + 1];
                if (MODE == EPI_SCATTER) {
                    float* dst = outf + (size_t)pid * HH + c0;
                    dst[0] = v0; dst[1] = v1;
                } else {
                    size_t base = (size_t)(mtile * 128 + mloc) * N + c0;
                    if (MODE == EPI_RELU_SPLIT || MODE == EPI_RELU_F32) {
                        v0 = fmaxf(v0, 0.f); v1 = fmaxf(v1, 0.f);
                    }
                    if (MODE == EPI_RELU_SPLIT) {
                        bf16 h0 = __float2bfloat16(v0), h1 = __float2bfloat16(v1);
                        outhi[base] = h0; outhi[base + 1] = h1;
                        outlo[base] = __float2bfloat16(v0 - __bfloat162float(h0));
                        outlo[base + 1] = __float2bfloat16(v1 - __bfloat162float(h1));
                    } else {
                        outf[base] = v0; outf[base + 1] = v1;
                    }
                }
            }
        }
    }
}

// ---------------- combine: moe = relu(w0*pair0 + w1*pair1), split to bf16 ----
__global__ void combine_kernel() {
    int idx = blockIdx.x * blockDim.x + threadIdx.x;   // NT*HH
    int t = idx >> 11;
    size_t a_i = (size_t)idx + (size_t)t * HH;
    float w0 = g_wval[2 * t], w1 = g_wval[2 * t + 1];
    float a = g_pair[a_i];
    float b = g_pair[a_i + HH];
    float v = fmaxf(fmaf(w0, a, w1 * b), 0.f);
    bf16 h = __float2bfloat16(v);
    g_moehi[idx] = h;
    g_moelo[idx] = __float2bfloat16(v - __bfloat162float(h));
}

// ---------------- launch ------------------------------------------------------
extern "C" void kernel_launch(void* const* d_in, const int* in_sizes, int n_in,
                              void* d_out, int out_size) {
    const float* x    = (const float*)d_in[0];
    const int*   ft   = (const int*)  d_in[1];
    const float* gw1  = (const float*)d_in[2];
    const float* gb1  = (const float*)d_in[3];
    const float* gw2  = (const float*)d_in[4];
    const float* gb2  = (const float*)d_in[5];
    const float* gw3  = (const float*)d_in[6];
    const float* gb3  = (const float*)d_in[7];
    const float* temb = (const float*)d_in[8];
    const float* tw   = (const float*)d_in[9];
    const float* tb   = (const float*)d_in[10];
    const float* ew   = (const float*)d_in[11];
    const float* eb   = (const float*)d_in[12];
    const float* ow   = (const float*)d_in[13];
    const float* ob   = (const float*)d_in[14];
    float* out = (float*)d_out;

    bf16 *xhi, *xlo, *h1hi, *h1lo, *w1hi, *w1lo, *w2hi, *w2lo, *ewhi, *ewlo, *owhi, *owlo, *mhi, *mlo;
    float *h2, *pair;
    cudaGetSymbolAddress((void**)&xhi, g_xhi);   cudaGetSymbolAddress((void**)&xlo, g_xlo);
    cudaGetSymbolAddress((void**)&h1hi, g_h1hi); cudaGetSymbolAddress((void**)&h1lo, g_h1lo);
    cudaGetSymbolAddress((void**)&w1hi, g_w1hi); cudaGetSymbolAddress((void**)&w1lo, g_w1lo);
    cudaGetSymbolAddress((void**)&w2hi, g_w2hi); cudaGetSymbolAddress((void**)&w2lo, g_w2lo);
    cudaGetSymbolAddress((void**)&ewhi, g_ewhi); cudaGetSymbolAddress((void**)&ewlo, g_ewlo);
    cudaGetSymbolAddress((void**)&owhi, g_owhi); cudaGetSymbolAddress((void**)&owlo, g_owlo);
    cudaGetSymbolAddress((void**)&mhi, g_moehi); cudaGetSymbolAddress((void**)&mlo, g_moelo);
    cudaGetSymbolAddress((void**)&h2, g_h2);     cudaGetSymbolAddress((void**)&pair, g_pair);

    cudaFuncSetAttribute(mma_gemm<EPI_RELU_SPLIT, false>, cudaFuncAttributeMaxDynamicSharedMemorySize, SMEM_TOTAL);
    cudaFuncSetAttribute(mma_gemm<EPI_RELU_F32,   false>, cudaFuncAttributeMaxDynamicSharedMemorySize, SMEM_TOTAL);
    cudaFuncSetAttribute(mma_gemm<EPI_F32,        false>, cudaFuncAttributeMaxDynamicSharedMemorySize, SMEM_TOTAL);
    cudaFuncSetAttribute(mma_gemm<EPI_SCATTER,    true>,  cudaFuncAttributeMaxDynamicSharedMemorySize, SMEM_TOTAL);

    zero_cnt_kernel<<<1, 32>>>();

    // conversions: x split; weights transpose+split to [N,K]
    split_x_kernel<<<(NT * DD) / 256, 256>>>(x);
    tsplit_kernel<<<dim3(GHA / 32, DD / 32, 1), dim3(32, 8)>>>(gw1, w1hi, w1lo, DD, GHA);
    tsplit_kernel<<<dim3(GHB / 32, GHA / 32, 1), dim3(32, 8)>>>(gw2, w2hi, w2lo, GHA, GHB);
    tsplit_kernel<<<dim3(HH / 32, DD / 32, NE), dim3(32, 8)>>>(ew, ewhi, ewlo, DD, HH);
    tsplit_kernel<<<dim3(DD / 32, HH / 32, 1), dim3(32, 8)>>>(ow, owhi, owlo, HH, DD);

    // gating MLP on tensor cores
    mma_gemm<EPI_RELU_SPLIT, false><<<dim3(GHA / 128, NT / 128), 256, SMEM_TOTAL>>>(
        xhi, xlo, w1hi, w1lo, gb1, nullptr, h1hi, h1lo, GHA, DD);
    mma_gemm<EPI_RELU_F32, false><<<dim3(GHB / 128, NT / 128), 256, SMEM_TOTAL>>>(
        h1hi, h1lo, w2hi, w2lo, gb2, h2, nullptr, nullptr, GHB, GHA);

    // routing
    gating_kernel<<<NT / 8, 256>>>(ft, gw3, gb3, temb, tw, tb);

    // selected-expert grouped GEMM (gathered A, scattered C)
    mma_gemm<EPI_SCATTER, true><<<dim3(HH / 128, MAX_MTILES), 256, SMEM_TOTAL>>>(
        xhi, xlo, ewhi, ewlo, eb, pair, nullptr, nullptr, HH, DD);

    // combine + relu + split
    combine_kernel<<<(NT * HH) / 256, 256>>>();

    // output projection
    mma_gemm<EPI_F32, false><<<dim3(DD / 128, NT / 128), 256, SMEM_TOTAL>>>(
        mhi, mlo, owhi, owlo, ob, out, nullptr, nullptr, DD, HH);
}